// round 6
// baseline (speedup 1.0000x reference)
#include <cuda_runtime.h>
#include <cuda_bf16.h>
#include <cstdint>

// LengthRegulator: out[b, t, :] = phoneme[b, tok(b,t), :]
// tok(b,t) = searchsorted_right(inclusive_cumsum(durations[b,:]), t), clip N-1.
// Shapes (fixed): B=16, N=256, D=512, T=2048. float32.
//
// All bulk data movement via 1D TMA (cp.async.bulk): gmem->smem loads of the
// distinct token rows, then per-frame smem->gmem stores. The LSU never touches
// the 67MB payload.

#define LR_B 16
#define LR_N 256
#define LR_D 512
#define LR_T 2048
#define FPB 16                       // frames per block
#define ROW_BYTES (LR_D * 4)         // 2048 bytes per frame row

__device__ __forceinline__ uint32_t smem_u32(const void* p) {
    uint32_t a;
    asm("{ .reg .u64 t; cvta.to.shared.u64 t, %1; cvt.u32.u64 %0, t; }"
        : "=r"(a) : "l"(p));
    return a;
}

__global__ __launch_bounds__(32)
void length_regulator_tma(const char* __restrict__ phoneme,
                          const int* __restrict__ durations,
                          char* __restrict__ out)
{
    __shared__ __align__(2048) char s_rows[FPB][ROW_BYTES];  // 32KB staging
    __shared__ int s_ends[LR_N];
    __shared__ __align__(8) unsigned long long s_mbar;

    const int b = blockIdx.y;
    const int frame_base = blockIdx.x * FPB;
    const int lane = threadIdx.x;

    const uint32_t mbar = smem_u32(&s_mbar);

    if (lane == 0) {
        asm volatile("mbarrier.init.shared.b64 [%0], %1;"
                     :: "r"(mbar), "r"(1u) : "memory");
    }

    // 1) shuffle scan of durations[b,:]: lane owns elements 8L..8L+7
    {
        const int4* drow = (const int4*)(durations + b * LR_N);
        int4 a = drow[lane * 2 + 0];
        int4 c = drow[lane * 2 + 1];
        int e0 = a.x;
        int e1 = e0 + a.y;
        int e2 = e1 + a.z;
        int e3 = e2 + a.w;
        int e4 = e3 + c.x;
        int e5 = e4 + c.y;
        int e6 = e5 + c.z;
        int e7 = e6 + c.w;
        int x = e7;
        #pragma unroll
        for (int off = 1; off < 32; off <<= 1) {
            int y = __shfl_up_sync(0xffffffffu, x, off);
            if (lane >= off) x += y;
        }
        const int excl = x - e7;
        s_ends[lane * 8 + 0] = e0 + excl;
        s_ends[lane * 8 + 1] = e1 + excl;
        s_ends[lane * 8 + 2] = e2 + excl;
        s_ends[lane * 8 + 3] = e3 + excl;
        s_ends[lane * 8 + 4] = e4 + excl;
        s_ends[lane * 8 + 5] = e5 + excl;
        s_ends[lane * 8 + 6] = e6 + excl;
        s_ends[lane * 8 + 7] = e7 + excl;
    }
    __syncwarp();

    // 2) lanes 0..15: token of frame (frame_base + lane)
    int tok = 0;
    if (lane < FPB) {
        const int t = frame_base + lane;
        int lo = 0, hi = LR_N;
        #pragma unroll
        for (int it = 0; it < 9; ++it) {
            if (lo < hi) {
                int mid = (lo + hi) >> 1;
                if (s_ends[mid] > t) hi = mid; else lo = mid + 1;
            }
        }
        tok = (lo < LR_N) ? lo : (LR_N - 1);
    }

    // 3) dedupe consecutive equal tokens -> slot assignment.
    //    slot(lane) = index of this lane's RUN LEADER among all leaders:
    //    inclusive popcount of leaders at lanes <= lane, minus 1.
    const int prev_tok = __shfl_up_sync(0xffffffffu, tok, 1);
    const bool active = (lane < FPB);
    const bool is_new = active && (lane == 0 || tok != prev_tok);
    const uint32_t new_mask = __ballot_sync(0xffffffffu, is_new);
    const int slot = __popc(new_mask & ((2u << lane) - 1)) - 1;
    const int nslots = __popc(new_mask);

    // 4) TMA loads: one 2KB bulk load per distinct token row
    if (lane == 0) {
        asm volatile("mbarrier.arrive.expect_tx.shared.b64 _, [%0], %1;"
                     :: "r"(mbar), "r"((uint32_t)(nslots * ROW_BYTES)) : "memory");
    }
    __syncwarp();
    if (is_new) {
        const char* src = phoneme + ((size_t)b * LR_N + tok) * ROW_BYTES;
        const uint32_t dst = smem_u32(&s_rows[slot][0]);
        asm volatile(
            "cp.async.bulk.shared::cluster.global.mbarrier::complete_tx::bytes "
            "[%0], [%1], %2, [%3];"
            :: "r"(dst), "l"(src), "r"((uint32_t)ROW_BYTES), "r"(mbar)
            : "memory");
    }

    // 5) wait for all loads
    {
        uint32_t done;
        asm volatile(
            "{\n\t.reg .pred p;\n\t"
            "mbarrier.try_wait.parity.shared.b64 p, [%1], %2;\n\t"
            "selp.b32 %0, 1, 0, p;\n\t}"
            : "=r"(done) : "r"(mbar), "r"(0u) : "memory");
        while (!done) {
            asm volatile(
                "{\n\t.reg .pred p;\n\t"
                "mbarrier.try_wait.parity.shared.b64 p, [%1], %2;\n\t"
                "selp.b32 %0, 1, 0, p;\n\t}"
                : "=r"(done) : "r"(mbar), "r"(0u) : "memory");
        }
    }
    __syncwarp();

    // 6) TMA stores: one 2KB bulk store per frame from its run-leader's slot
    if (active) {
        char* dst = out + ((size_t)b * LR_T + frame_base + lane) * ROW_BYTES;
        const uint32_t src = smem_u32(&s_rows[slot][0]);
        asm volatile(
            "cp.async.bulk.global.shared::cta.bulk_group [%0], [%1], %2;"
            :: "l"(dst), "r"(src), "r"((uint32_t)ROW_BYTES)
            : "memory");
    }
    asm volatile("cp.async.bulk.commit_group;" ::: "memory");
    asm volatile("cp.async.bulk.wait_group 0;" ::: "memory");
}

extern "C" void kernel_launch(void* const* d_in, const int* in_sizes, int n_in,
                              void* d_out, int out_size)
{
    const char* phoneme   = (const char*)d_in[0];   // (B, N, D) f32
    const int*  durations = (const int*)d_in[1];    // (B, N) i32
    char*       out       = (char*)d_out;           // (B, T, D) f32

    dim3 grid(LR_T / FPB, LR_B);    // (128, 16) = 2048 blocks
    length_regulator_tma<<<grid, 32>>>(phoneme, durations, out);
}